// round 15
// baseline (speedup 1.0000x reference)
#include <cuda_runtime.h>
#include <cuda_fp16.h>
#include <math.h>
#include <stdint.h>

#define NN 50000
#define NE 640000
#define DH 128
#define NG 1024
#define NL 3
#define BN_EPS 1e-5f

#define SCAN_T 256
#define SCAN_NB ((NN + SCAN_T - 1) / SCAN_T)   // 196

__device__ __forceinline__ uint32_t smem_to_u32(const void* p) {
    uint32_t a;
    asm("{ .reg .u64 t; cvta.to.shared.u64 t, %1; cvt.u32.u64 %0, t; }" : "=r"(a) : "l"(p));
    return a;
}

// ---------------- scratch ----------------
__device__ int   g_deg[NN];
__device__ int   g_off[NN + 1];
__device__ int   g_cur[NN];
__device__ float g_dinv[NN];
__device__ int   g_csr[NE];
__device__ int   g_bsum[SCAN_NB];
__device__ __half g_gbuf[(size_t)NN * DH];     // fp16 messages
__device__ __half g_hag[(size_t)NN * DH];      // fp16 aggregated h
__device__ float g_sum[NL * DH];
__device__ float g_sq[NL * DH];
__device__ int   g_cnt[NG];
__device__ unsigned short g_whi[NL * 16384];   // W^T fp16, swizzled 32KB/layer

__device__ __forceinline__ float elu1(float v) {
    return v > 0.f ? v : (__expf(v) - 1.f);
}

__device__ __forceinline__ int swz_off(int r, int kchunk) {
    return r * 256 + ((kchunk ^ (r & 7)) << 4);
}

// ---------------- launch 1: init everything + W convert ----------------
__global__ void k_init_all(const float* __restrict__ Ws) {
    int i = blockIdx.x * 256 + threadIdx.x;
    if (i < NN) g_deg[i] = 0;
    if (i < NL * DH) { g_sum[i] = 0.f; g_sq[i] = 0.f; }
    if (i < NG) g_cnt[i] = 0;
    if (i < NL * 16384) {
        int l = i >> 14;
        int rem = i & 16383;
        int n = rem & 127;
        int k = rem >> 7;
        float w = Ws[(size_t)l * 16384 + k * 128 + n];
        int off = swz_off(n, k >> 3) + (k & 7) * 2;
        g_whi[l * 16384 + (off >> 1)] = __half_as_ushort(__float2half_rn(w));
    }
}

// ---------------- launch 2: degree histogram + graph counts ----------------
__global__ void k_deg(const int* __restrict__ dst, const int* __restrict__ bidx) {
    int e = blockIdx.x * blockDim.x + threadIdx.x;
    if (e < NE) atomicAdd(&g_deg[dst[e]], 1);
    if (e < NN) atomicAdd(&g_cnt[bidx[e]], 1);
}

// ---------------- launch 3: block sums + dinv ----------------
__global__ void __launch_bounds__(SCAN_T) k_bsum() {
    int i = blockIdx.x * SCAN_T + threadIdx.x;
    int v = (i < NN) ? g_deg[i] : 0;
    if (i < NN) g_dinv[i] = rsqrtf((float)(v + 1));   // +1 self loop
    #pragma unroll
    for (int o = 16; o; o >>= 1) v += __shfl_down_sync(0xffffffffu, v, o);
    __shared__ int ws[SCAN_T / 32];
    if ((threadIdx.x & 31) == 0) ws[threadIdx.x >> 5] = v;
    __syncthreads();
    if (threadIdx.x < SCAN_T / 32) {
        int s = ws[threadIdx.x];
        #pragma unroll
        for (int o = SCAN_T / 64; o; o >>= 1) s += __shfl_down_sync(0xffu, s, o);
        if (threadIdx.x == 0) g_bsum[blockIdx.x] = s;
    }
}

// ---------------- local scan with self-computed block offset ----------------
__global__ void __launch_bounds__(SCAN_T) k_lscan() {
    int tid = threadIdx.x;
    int lane = tid & 31, wid = tid >> 5;
    int bid = blockIdx.x;

    __shared__ int s_boff;
    __shared__ int wred[SCAN_T / 32];
    {
        int bv = (tid < bid) ? g_bsum[tid] : 0;
        #pragma unroll
        for (int o = 16; o; o >>= 1) bv += __shfl_down_sync(0xffffffffu, bv, o);
        if (lane == 0) wred[wid] = bv;
        __syncthreads();
        if (tid == 0) {
            int s = 0;
            #pragma unroll
            for (int w = 0; w < SCAN_T / 32; ++w) s += wred[w];
            s_boff = s;
        }
        __syncthreads();
    }

    int i = bid * SCAN_T + tid;
    int v = (i < NN) ? g_deg[i] : 0;
    int incl = v;
    #pragma unroll
    for (int o = 1; o < 32; o <<= 1) {
        int t = __shfl_up_sync(0xffffffffu, incl, o);
        if (lane >= o) incl += t;
    }
    __shared__ int wtot[SCAN_T / 32];
    if (lane == 31) wtot[wid] = incl;
    __syncthreads();
    if (tid < SCAN_T / 32) {
        int s = wtot[tid];
        int si = s;
        #pragma unroll
        for (int o = 1; o < SCAN_T / 32; o <<= 1) {
            int t = __shfl_up_sync(0xffu, si, o);
            if (tid >= o) si += t;
        }
        wtot[tid] = si - s;
    }
    __syncthreads();
    int excl = incl - v + wtot[wid] + s_boff;
    if (i < NN) {
        g_off[i] = excl;
        g_cur[i] = excl;
        if (i == NN - 1) g_off[NN] = excl + v;
    }
}

__global__ void k_fill(const int* __restrict__ src, const int* __restrict__ dst) {
    int e = blockIdx.x * blockDim.x + threadIdx.x;
    if (e < NE) {
        int d = dst[e];
        int pos = atomicAdd(&g_cur[d], 1);
        g_csr[pos] = src[e];
    }
}

// ---------------- HMMA GEMM: grid=391, pure fp16, single pass (R12 shape) ---
#define SA    0
#define SB    32768
#define SC_OFF 65536
#define SH_OFF 66048
#define SM_TOTAL 66560

__device__ __forceinline__ void ldsm4(uint32_t& r0, uint32_t& r1, uint32_t& r2,
                                      uint32_t& r3, uint32_t addr) {
    asm volatile("ldmatrix.sync.aligned.m8n8.x4.shared.b16 {%0,%1,%2,%3}, [%4];"
                 : "=r"(r0), "=r"(r1), "=r"(r2), "=r"(r3) : "r"(addr));
}
__device__ __forceinline__ void mma16816(float* d, const uint32_t* a, const uint32_t* b) {
    asm volatile(
        "mma.sync.aligned.m16n8k16.row.col.f32.f16.f16.f32 "
        "{%0,%1,%2,%3}, {%4,%5,%6,%7}, {%8,%9}, {%0,%1,%2,%3};"
        : "+f"(d[0]), "+f"(d[1]), "+f"(d[2]), "+f"(d[3])
        : "r"(a[0]), "r"(a[1]), "r"(a[2]), "r"(a[3]), "r"(b[0]), "r"(b[1]));
}
#define CP_ASYNC16(dst, src) \
    asm volatile("cp.async.cg.shared.global [%0], [%1], 16;" :: "r"(dst), "l"(src))
#define CP_COMMIT() asm volatile("cp.async.commit_group;" ::: "memory")
#define CP_WAIT0() asm volatile("cp.async.wait_group 0;" ::: "memory")

__global__ void __launch_bounds__(256, 2) k_gemm_tc(int layer, const float* __restrict__ x,
                                                    const float* __restrict__ gamma,
                                                    const float* __restrict__ beta) {
    extern __shared__ char sm[];
    uint32_t sm_u = smem_to_u32(sm);
    int tid = threadIdx.x;
    int wid = tid >> 5, lane = tid & 31;

    // --- B tile (32KB) via cp.async
    {
        const char* wh = (const char*)(g_whi + layer * 16384) + tid * 16;
        uint32_t bh = sm_u + SB + tid * 16;
        #pragma unroll
        for (int i = 0; i < 8; ++i)
            CP_ASYNC16(bh + i * 4096, wh + i * 4096);
        CP_COMMIT();
    }

    // --- BN scale/shift into smem
    float* scp = (float*)(sm + SC_OFF);
    float* shp = (float*)(sm + SH_OFF);
    if (layer > 0 && tid < DH) {
        float m = g_sum[(layer - 1) * DH + tid] * (1.f / NN);
        float var = g_sq[(layer - 1) * DH + tid] * (1.f / NN) - m * m;
        float rs = rsqrtf(var + BN_EPS);
        float scv = gamma[tid] * rs;
        scp[tid] = scv;
        shp[tid] = beta[tid] - m * scv;
    }
    if (layer > 0) __syncthreads();   // publish scp/shp before conversion reads

    // --- convert A' half-row per thread (fused BN+ELU for layer>0)
    {
        int row = tid >> 1, hq = tid & 1;
        int gr = blockIdx.x * 128 + row;
        if (gr < NN) {
            #pragma unroll
            for (int c8 = 0; c8 < 8; ++c8) {
                int kc = hq * 8 + c8;
                int k0 = kc * 8;
                float f[8];
                if (layer == 0) {
                    float4 v0 = *(const float4*)(x + (size_t)gr * DH + k0);
                    float4 v1 = *(const float4*)(x + (size_t)gr * DH + k0 + 4);
                    f[0] = v0.x; f[1] = v0.y; f[2] = v0.z; f[3] = v0.w;
                    f[4] = v1.x; f[5] = v1.y; f[6] = v1.z; f[7] = v1.w;
                } else {
                    int4 u = *(const int4*)(g_hag + (size_t)gr * DH + k0);
                    float2 p0 = __half22float2(*(__half2*)&u.x);
                    float2 p1 = __half22float2(*(__half2*)&u.y);
                    float2 p2 = __half22float2(*(__half2*)&u.z);
                    float2 p3 = __half22float2(*(__half2*)&u.w);
                    f[0] = p0.x; f[1] = p0.y; f[2] = p1.x; f[3] = p1.y;
                    f[4] = p2.x; f[5] = p2.y; f[6] = p3.x; f[7] = p3.y;
                    #pragma unroll
                    for (int c = 0; c < 8; ++c)
                        f[c] = elu1(fmaf(f[c], scp[k0 + c], shp[k0 + c]));
                }
                uint32_t hp[4];
                #pragma unroll
                for (int p = 0; p < 4; ++p) {
                    __half2 h2 = __floats2half2_rn(f[p * 2], f[p * 2 + 1]);
                    hp[p] = *(uint32_t*)&h2;
                }
                *(int4*)(sm + SA + swz_off(row, kc)) = make_int4(hp[0], hp[1], hp[2], hp[3]);
            }
        } else {
            int4 z = make_int4(0, 0, 0, 0);
            #pragma unroll
            for (int c8 = 0; c8 < 8; ++c8)
                *(int4*)(sm + SA + swz_off(row, hq * 8 + c8)) = z;
        }
    }
    CP_WAIT0();
    __syncthreads();

    int warp_m = (wid & 3) * 32;
    int warp_n = (wid >> 2) * 64;

    float acc[2][8][4];
    #pragma unroll
    for (int i = 0; i < 2; ++i)
        #pragma unroll
        for (int j = 0; j < 8; ++j)
            #pragma unroll
            for (int c = 0; c < 4; ++c) acc[i][j][c] = 0.f;

    int sub = lane >> 3, l7 = lane & 7;
    int a_r0 = warp_m + (sub & 1) * 8 + l7;
    int a_cadd = sub >> 1;
    int b_nsel = (sub >> 1) * 8 + l7;
    int b_cadd = sub & 1;

    uint32_t aB = sm_u + SA, bB = sm_u + SB;
    #pragma unroll
    for (int ks = 0; ks < 8; ++ks) {
        int a_kc = ks * 2 + a_cadd;
        int b_kc = ks * 2 + b_cadd;

        uint32_t a[2][4];
        #pragma unroll
        for (int mf = 0; mf < 2; ++mf)
            ldsm4(a[mf][0], a[mf][1], a[mf][2], a[mf][3],
                  aB + swz_off(a_r0 + mf * 16, a_kc));

        uint32_t b[8][2];
        #pragma unroll
        for (int p = 0; p < 4; ++p)
            ldsm4(b[p * 2][0], b[p * 2][1], b[p * 2 + 1][0], b[p * 2 + 1][1],
                  bB + swz_off(warp_n + p * 16 + b_nsel, b_kc));

        #pragma unroll
        for (int mf = 0; mf < 2; ++mf)
            #pragma unroll
            for (int nf = 0; nf < 8; ++nf)
                mma16816(acc[mf][nf], a[mf], b[nf]);
    }

    // --- epilogue: scale by dinv, convert fp16, store
    int qr = lane >> 2, qc = (lane & 3) * 2;
    #pragma unroll
    for (int mf = 0; mf < 2; ++mf) {
        int r0 = blockIdx.x * 128 + warp_m + mf * 16 + qr;
        int r1 = r0 + 8;
        float d0 = (r0 < NN) ? g_dinv[r0] : 0.f;
        float d1 = (r1 < NN) ? g_dinv[r1] : 0.f;
        #pragma unroll
        for (int nf = 0; nf < 8; ++nf) {
            int col = warp_n + nf * 8 + qc;
            if (r0 < NN) {
                __half2 o = __floats2half2_rn(acc[mf][nf][0] * d0, acc[mf][nf][1] * d0);
                *(__half2*)(g_gbuf + (size_t)r0 * DH + col) = o;
            }
            if (r1 < NN) {
                __half2 o = __floats2half2_rn(acc[mf][nf][2] * d1, acc[mf][nf][3] * d1);
                *(__half2*)(g_gbuf + (size_t)r1 * DH + col) = o;
            }
        }
    }
}

// ---------------- aggregation: fp16 gather (MLP 8), fp32 accum, fp16 h ------
__device__ __forceinline__ void add_h4(float4& a, uint2 u) {
    float2 p0 = __half22float2(*(__half2*)&u.x);
    float2 p1 = __half22float2(*(__half2*)&u.y);
    a.x += p0.x; a.y += p0.y; a.z += p1.x; a.w += p1.y;
}

__global__ void __launch_bounds__(256) k_agg(int layer, const float* __restrict__ bias,
                                             float* __restrict__ out) {
    if (out) {
        int idx = blockIdx.x * 256 + threadIdx.x;
        if (idx < NG * DH) out[idx] = 0.f;
    }
    __shared__ float s_sum[DH];
    __shared__ float s_sq[DH];
    int tid = threadIdx.x;
    if (tid < DH) { s_sum[tid] = 0.f; s_sq[tid] = 0.f; }
    __syncthreads();

    int warp = tid >> 5, lane = tid & 31;
    int base = blockIdx.x * 32 + warp * 4;
    int f = lane * 4;
    float4 b = ((const float4*)bias)[lane];

    float ls0 = 0.f, ls1 = 0.f, ls2 = 0.f, ls3 = 0.f;
    float lq0 = 0.f, lq1 = 0.f, lq2 = 0.f, lq3 = 0.f;

    int nend = base + 4 < NN ? base + 4 : NN;
    for (int node = base; node < nend; ++node) {
        float4 a0 = make_float4(0.f, 0.f, 0.f, 0.f);
        float4 a1 = make_float4(0.f, 0.f, 0.f, 0.f);
        add_h4(a0, *(const uint2*)(g_gbuf + (size_t)node * DH + f));   // self
        int s = g_off[node], e2 = g_off[node + 1];
        int p = s;
        for (; p + 7 < e2; p += 8) {
            int i0 = g_csr[p],     i1 = g_csr[p + 1], i2 = g_csr[p + 2], i3 = g_csr[p + 3];
            int i4 = g_csr[p + 4], i5 = g_csr[p + 5], i6 = g_csr[p + 6], i7 = g_csr[p + 7];
            uint2 u0 = *(const uint2*)(g_gbuf + (size_t)i0 * DH + f);
            uint2 u1 = *(const uint2*)(g_gbuf + (size_t)i1 * DH + f);
            uint2 u2 = *(const uint2*)(g_gbuf + (size_t)i2 * DH + f);
            uint2 u3 = *(const uint2*)(g_gbuf + (size_t)i3 * DH + f);
            uint2 u4 = *(const uint2*)(g_gbuf + (size_t)i4 * DH + f);
            uint2 u5 = *(const uint2*)(g_gbuf + (size_t)i5 * DH + f);
            uint2 u6 = *(const uint2*)(g_gbuf + (size_t)i6 * DH + f);
            uint2 u7 = *(const uint2*)(g_gbuf + (size_t)i7 * DH + f);
            add_h4(a0, u0); add_h4(a1, u1); add_h4(a0, u2); add_h4(a1, u3);
            add_h4(a0, u4); add_h4(a1, u5); add_h4(a0, u6); add_h4(a1, u7);
        }
        for (; p + 1 < e2; p += 2) {
            int i0 = g_csr[p], i1 = g_csr[p + 1];
            uint2 u0 = *(const uint2*)(g_gbuf + (size_t)i0 * DH + f);
            uint2 u1 = *(const uint2*)(g_gbuf + (size_t)i1 * DH + f);
            add_h4(a0, u0); add_h4(a1, u1);
        }
        if (p < e2) {
            int i0 = g_csr[p];
            add_h4(a0, *(const uint2*)(g_gbuf + (size_t)i0 * DH + f));
        }
        float di = g_dinv[node];
        float4 h;
        h.x = fmaf(di, a0.x + a1.x, b.x);
        h.y = fmaf(di, a0.y + a1.y, b.y);
        h.z = fmaf(di, a0.z + a1.z, b.z);
        h.w = fmaf(di, a0.w + a1.w, b.w);
        __half2 o0 = __floats2half2_rn(h.x, h.y);
        __half2 o1 = __floats2half2_rn(h.z, h.w);
        uint2 ov;
        ov.x = *(uint32_t*)&o0;
        ov.y = *(uint32_t*)&o1;
        *(uint2*)(g_hag + (size_t)node * DH + f) = ov;

        ls0 += h.x; lq0 += h.x * h.x;
        ls1 += h.y; lq1 += h.y * h.y;
        ls2 += h.z; lq2 += h.z * h.z;
        ls3 += h.w; lq3 += h.w * h.w;
    }
    atomicAdd(&s_sum[f + 0], ls0); atomicAdd(&s_sq[f + 0], lq0);
    atomicAdd(&s_sum[f + 1], ls1); atomicAdd(&s_sq[f + 1], lq1);
    atomicAdd(&s_sum[f + 2], ls2); atomicAdd(&s_sq[f + 2], lq2);
    atomicAdd(&s_sum[f + 3], ls3); atomicAdd(&s_sq[f + 3], lq3);
    __syncthreads();
    if (tid < DH) {
        atomicAdd(&g_sum[layer * DH + tid], s_sum[tid]);
        atomicAdd(&g_sq[layer * DH + tid], s_sq[tid]);
    }
}

// ---------------- pooling: batch-preloaded rows, pre-scaled atomics ----------
__global__ void __launch_bounds__(256) k_pool(const int* __restrict__ bidx,
                                              const float* __restrict__ gamma,
                                              const float* __restrict__ beta,
                                              float* __restrict__ out) {
    int tid = threadIdx.x;
    int warp = (blockIdx.x * 8 + (tid >> 5));
    int base = warp * 8;
    if (base >= NN) return;
    int lane = tid & 31;
    int f = lane * 4;
    const int L2 = (NL - 1) * DH;
    float s[4], t[4];
    #pragma unroll
    for (int c = 0; c < 4; ++c) {
        float m = g_sum[L2 + f + c] * (1.f / NN);
        float var = g_sq[L2 + f + c] * (1.f / NN) - m * m;
        float rs = rsqrtf(var + BN_EPS);
        s[c] = gamma[f + c] * rs;
        t[c] = beta[f + c] - m * s[c];
    }

    int cnt = base + 8 < NN ? 8 : NN - base;
    uint2 r[8];
    int bi[8];
    #pragma unroll
    for (int i = 0; i < 8; ++i) {
        if (i < cnt) {
            r[i] = *(const uint2*)(g_hag + (size_t)(base + i) * DH + f);
            bi[i] = bidx[base + i];
        }
    }

    float a0 = 0.f, a1 = 0.f, a2 = 0.f, a3 = 0.f;
    int cur = bi[0];
    #pragma unroll
    for (int i = 0; i < 8; ++i) {
        if (i >= cnt) break;
        if (bi[i] != cur) {
            float inv = 1.f / fmaxf((float)g_cnt[cur], 1.f);
            float* o = out + (size_t)cur * DH + f;
            atomicAdd(o + 0, a0 * inv); atomicAdd(o + 1, a1 * inv);
            atomicAdd(o + 2, a2 * inv); atomicAdd(o + 3, a3 * inv);
            a0 = a1 = a2 = a3 = 0.f;
            cur = bi[i];
        }
        float2 p0 = __half22float2(*(__half2*)&r[i].x);
        float2 p1 = __half22float2(*(__half2*)&r[i].y);
        a0 += elu1(fmaf(p0.x, s[0], t[0]));
        a1 += elu1(fmaf(p0.y, s[1], t[1]));
        a2 += elu1(fmaf(p1.x, s[2], t[2]));
        a3 += elu1(fmaf(p1.y, s[3], t[3]));
    }
    float inv = 1.f / fmaxf((float)g_cnt[cur], 1.f);
    float* o = out + (size_t)cur * DH + f;
    atomicAdd(o + 0, a0 * inv); atomicAdd(o + 1, a1 * inv);
    atomicAdd(o + 2, a2 * inv); atomicAdd(o + 3, a3 * inv);
}

// ---------------- launch ----------------
extern "C" void kernel_launch(void* const* d_in, const int* in_sizes, int n_in,
                              void* d_out, int out_size) {
    const float* x      = (const float*)d_in[0];
    const float* Ws     = (const float*)d_in[1];
    const float* bs     = (const float*)d_in[2];
    const float* gammas = (const float*)d_in[3];
    const float* betas  = (const float*)d_in[4];
    const int*   ei     = (const int*)d_in[5];
    const int*   bidx   = (const int*)d_in[6];
    float*       out    = (float*)d_out;

    const int* src = ei;
    const int* dst = ei + NE;

    cudaFuncSetAttribute(k_gemm_tc, cudaFuncAttributeMaxDynamicSharedMemorySize, SM_TOTAL);

    int gemm_grid = (NN + 127) / 128;   // 391
    int agg_grid = (NN + 31) / 32;

    k_init_all<<<(NN + 255) / 256, 256>>>(Ws);                      // 1
    k_deg<<<(NE + 255) / 256, 256>>>(dst, bidx);                    // 2
    k_bsum<<<SCAN_NB, SCAN_T>>>();                                  // 3 (+dinv)
    k_gemm_tc<<<gemm_grid, 256, SM_TOTAL>>>(0, x, gammas, betas);   // 4 <- ncu slot
    k_lscan<<<SCAN_NB, SCAN_T>>>();                                 // 5 (+bscan)
    k_fill<<<(NE + 255) / 256, 256>>>(src, dst);                    // 6

    k_agg<<<agg_grid, 256>>>(0, bs, nullptr);                       // 7
    k_gemm_tc<<<gemm_grid, 256, SM_TOTAL>>>(1, x, gammas + DH, betas + DH);
    k_agg<<<agg_grid, 256>>>(1, bs + DH, nullptr);
    k_gemm_tc<<<gemm_grid, 256, SM_TOTAL>>>(2, x, gammas + 2 * DH, betas + 2 * DH);
    k_agg<<<agg_grid, 256>>>(2, bs + 2 * DH, out);                  // zeroes out

    int pool_grid = (NN + 63) / 64;
    k_pool<<<pool_grid, 256>>>(bidx, gammas + 2 * DH, betas + 2 * DH, out);
}

// round 16
// speedup vs baseline: 1.4519x; 1.4519x over previous
#include <cuda_runtime.h>
#include <cuda_fp16.h>
#include <math.h>
#include <stdint.h>

#define NN 50000
#define NE 640000
#define DH 128
#define NG 1024
#define NL 3
#define BN_EPS 1e-5f

#define SCAN_T 256
#define SCAN_NB ((NN + SCAN_T - 1) / SCAN_T)   // 196

#define GEMM_TILES ((NN + 127) / 128)          // 391
#define GEMM_GRID 296                          // 2 CTAs x 148 SMs resident

__device__ __forceinline__ uint32_t smem_to_u32(const void* p) {
    uint32_t a;
    asm("{ .reg .u64 t; cvta.to.shared.u64 t, %1; cvt.u32.u64 %0, t; }" : "=r"(a) : "l"(p));
    return a;
}

// ---------------- scratch ----------------
__device__ int   g_deg[NN];
__device__ int   g_off[NN + 1];
__device__ int   g_cur[NN];
__device__ float g_dinv[NN];
__device__ int   g_csr[NE];
__device__ int   g_bsum[SCAN_NB];
__device__ __half g_gbuf[(size_t)NN * DH];     // fp16 messages
__device__ __half g_hag[(size_t)NN * DH];      // fp16 aggregated h
__device__ float g_sum[NL * DH];
__device__ float g_sq[NL * DH];
__device__ int   g_cnt[NG];
__device__ unsigned short g_whi[NL * 16384];   // W^T fp16, swizzled 32KB/layer

__device__ __forceinline__ float elu1(float v) {
    return v > 0.f ? v : (__expf(v) - 1.f);
}

__device__ __forceinline__ int swz_off(int r, int kchunk) {
    return r * 256 + ((kchunk ^ (r & 7)) << 4);
}

// ---------------- launch 1: init everything + W convert ----------------
__global__ void k_init_all(const float* __restrict__ Ws) {
    int i = blockIdx.x * 256 + threadIdx.x;
    if (i < NN) g_deg[i] = 0;
    if (i < NL * DH) { g_sum[i] = 0.f; g_sq[i] = 0.f; }
    if (i < NG) g_cnt[i] = 0;
    if (i < NL * 16384) {
        int l = i >> 14;
        int rem = i & 16383;
        int n = rem & 127;
        int k = rem >> 7;
        float w = Ws[(size_t)l * 16384 + k * 128 + n];
        int off = swz_off(n, k >> 3) + (k & 7) * 2;
        g_whi[l * 16384 + (off >> 1)] = __half_as_ushort(__float2half_rn(w));
    }
}

// ---------------- launch 2: degree histogram + graph counts ----------------
__global__ void k_deg(const int* __restrict__ dst, const int* __restrict__ bidx) {
    int e = blockIdx.x * blockDim.x + threadIdx.x;
    if (e < NE) atomicAdd(&g_deg[dst[e]], 1);
    if (e < NN) atomicAdd(&g_cnt[bidx[e]], 1);
}

// ---------------- launch 3: block sums + dinv ----------------
__global__ void __launch_bounds__(SCAN_T) k_bsum() {
    int i = blockIdx.x * SCAN_T + threadIdx.x;
    int v = (i < NN) ? g_deg[i] : 0;
    if (i < NN) g_dinv[i] = rsqrtf((float)(v + 1));   // +1 self loop
    #pragma unroll
    for (int o = 16; o; o >>= 1) v += __shfl_down_sync(0xffffffffu, v, o);
    __shared__ int ws[SCAN_T / 32];
    if ((threadIdx.x & 31) == 0) ws[threadIdx.x >> 5] = v;
    __syncthreads();
    if (threadIdx.x < SCAN_T / 32) {
        int s = ws[threadIdx.x];
        #pragma unroll
        for (int o = SCAN_T / 64; o; o >>= 1) s += __shfl_down_sync(0xffu, s, o);
        if (threadIdx.x == 0) g_bsum[blockIdx.x] = s;
    }
}

// ---------------- local scan with self-computed block offset ----------------
__global__ void __launch_bounds__(SCAN_T) k_lscan() {
    int tid = threadIdx.x;
    int lane = tid & 31, wid = tid >> 5;
    int bid = blockIdx.x;

    __shared__ int s_boff;
    __shared__ int wred[SCAN_T / 32];
    {
        int bv = (tid < bid) ? g_bsum[tid] : 0;
        #pragma unroll
        for (int o = 16; o; o >>= 1) bv += __shfl_down_sync(0xffffffffu, bv, o);
        if (lane == 0) wred[wid] = bv;
        __syncthreads();
        if (tid == 0) {
            int s = 0;
            #pragma unroll
            for (int w = 0; w < SCAN_T / 32; ++w) s += wred[w];
            s_boff = s;
        }
        __syncthreads();
    }

    int i = bid * SCAN_T + tid;
    int v = (i < NN) ? g_deg[i] : 0;
    int incl = v;
    #pragma unroll
    for (int o = 1; o < 32; o <<= 1) {
        int t = __shfl_up_sync(0xffffffffu, incl, o);
        if (lane >= o) incl += t;
    }
    __shared__ int wtot[SCAN_T / 32];
    if (lane == 31) wtot[wid] = incl;
    __syncthreads();
    if (tid < SCAN_T / 32) {
        int s = wtot[tid];
        int si = s;
        #pragma unroll
        for (int o = 1; o < SCAN_T / 32; o <<= 1) {
            int t = __shfl_up_sync(0xffu, si, o);
            if (tid >= o) si += t;
        }
        wtot[tid] = si - s;
    }
    __syncthreads();
    int excl = incl - v + wtot[wid] + s_boff;
    if (i < NN) {
        g_off[i] = excl;
        g_cur[i] = excl;
        if (i == NN - 1) g_off[NN] = excl + v;
    }
}

__global__ void k_fill(const int* __restrict__ src, const int* __restrict__ dst) {
    int e = blockIdx.x * blockDim.x + threadIdx.x;
    if (e < NE) {
        int d = dst[e];
        int pos = atomicAdd(&g_cur[d], 1);
        g_csr[pos] = src[e];
    }
}

// ---------------- HMMA GEMM: persistent 296-CTA, pure fp16, single pass ----
#define SA    0
#define SB    32768
#define SC_OFF 65536
#define SH_OFF 66048
#define SM_TOTAL 66560

__device__ __forceinline__ void ldsm4(uint32_t& r0, uint32_t& r1, uint32_t& r2,
                                      uint32_t& r3, uint32_t addr) {
    asm volatile("ldmatrix.sync.aligned.m8n8.x4.shared.b16 {%0,%1,%2,%3}, [%4];"
                 : "=r"(r0), "=r"(r1), "=r"(r2), "=r"(r3) : "r"(addr));
}
__device__ __forceinline__ void mma16816(float* d, const uint32_t* a, const uint32_t* b) {
    asm volatile(
        "mma.sync.aligned.m16n8k16.row.col.f32.f16.f16.f32 "
        "{%0,%1,%2,%3}, {%4,%5,%6,%7}, {%8,%9}, {%0,%1,%2,%3};"
        : "+f"(d[0]), "+f"(d[1]), "+f"(d[2]), "+f"(d[3])
        : "r"(a[0]), "r"(a[1]), "r"(a[2]), "r"(a[3]), "r"(b[0]), "r"(b[1]));
}
#define CP_ASYNC16(dst, src) \
    asm volatile("cp.async.cg.shared.global [%0], [%1], 16;" :: "r"(dst), "l"(src))
#define CP_COMMIT() asm volatile("cp.async.commit_group;" ::: "memory")
#define CP_WAIT0() asm volatile("cp.async.wait_group 0;" ::: "memory")

__global__ void __launch_bounds__(256, 2) k_gemm_tc(int layer, const float* __restrict__ x,
                                                    const float* __restrict__ gamma,
                                                    const float* __restrict__ beta) {
    extern __shared__ char sm[];
    uint32_t sm_u = smem_to_u32(sm);
    int tid = threadIdx.x;
    int wid = tid >> 5, lane = tid & 31;

    // --- once per CTA: B tile (32KB) via cp.async (stays in flight during
    //     BN setup + first-tile conversion below)
    {
        const char* wh = (const char*)(g_whi + layer * 16384) + tid * 16;
        uint32_t bh = sm_u + SB + tid * 16;
        #pragma unroll
        for (int i = 0; i < 8; ++i)
            CP_ASYNC16(bh + i * 4096, wh + i * 4096);
        CP_COMMIT();
    }

    // --- once per CTA: BN scale/shift into smem
    float* scp = (float*)(sm + SC_OFF);
    float* shp = (float*)(sm + SH_OFF);
    if (layer > 0 && tid < DH) {
        float m = g_sum[(layer - 1) * DH + tid] * (1.f / NN);
        float var = g_sq[(layer - 1) * DH + tid] * (1.f / NN) - m * m;
        float rs = rsqrtf(var + BN_EPS);
        float scv = gamma[tid] * rs;
        scp[tid] = scv;
        shp[tid] = beta[tid] - m * scv;
    }
    __syncthreads();   // publish scp/shp before any conversion reads them

    int warp_m = (wid & 3) * 32;
    int warp_n = (wid >> 2) * 64;
    int sub = lane >> 3, l7 = lane & 7;
    int a_r0 = warp_m + (sub & 1) * 8 + l7;
    int a_cadd = sub >> 1;
    int b_nsel = (sub >> 1) * 8 + l7;
    int b_cadd = sub & 1;
    int row = tid >> 1, hq = tid & 1;
    uint32_t aB = sm_u + SA, bB = sm_u + SB;

    bool first = true;
    for (int tile = blockIdx.x; tile < GEMM_TILES; tile += GEMM_GRID) {
        // --- convert A' half-row per thread (fused BN+ELU for layer>0)
        int gr = tile * 128 + row;
        if (gr < NN) {
            #pragma unroll
            for (int c8 = 0; c8 < 8; ++c8) {
                int kc = hq * 8 + c8;
                int k0 = kc * 8;
                float f[8];
                if (layer == 0) {
                    float4 v0 = *(const float4*)(x + (size_t)gr * DH + k0);
                    float4 v1 = *(const float4*)(x + (size_t)gr * DH + k0 + 4);
                    f[0] = v0.x; f[1] = v0.y; f[2] = v0.z; f[3] = v0.w;
                    f[4] = v1.x; f[5] = v1.y; f[6] = v1.z; f[7] = v1.w;
                } else {
                    int4 u = *(const int4*)(g_hag + (size_t)gr * DH + k0);
                    float2 p0 = __half22float2(*(__half2*)&u.x);
                    float2 p1 = __half22float2(*(__half2*)&u.y);
                    float2 p2 = __half22float2(*(__half2*)&u.z);
                    float2 p3 = __half22float2(*(__half2*)&u.w);
                    f[0] = p0.x; f[1] = p0.y; f[2] = p1.x; f[3] = p1.y;
                    f[4] = p2.x; f[5] = p2.y; f[6] = p3.x; f[7] = p3.y;
                    #pragma unroll
                    for (int c = 0; c < 8; ++c)
                        f[c] = elu1(fmaf(f[c], scp[k0 + c], shp[k0 + c]));
                }
                uint32_t hp[4];
                #pragma unroll
                for (int p = 0; p < 4; ++p) {
                    __half2 h2 = __floats2half2_rn(f[p * 2], f[p * 2 + 1]);
                    hp[p] = *(uint32_t*)&h2;
                }
                *(int4*)(sm + SA + swz_off(row, kc)) = make_int4(hp[0], hp[1], hp[2], hp[3]);
            }
        } else {
            int4 z = make_int4(0, 0, 0, 0);
            #pragma unroll
            for (int c8 = 0; c8 < 8; ++c8)
                *(int4*)(sm + SA + swz_off(row, hq * 8 + c8)) = z;
        }
        if (first) { CP_WAIT0(); first = false; }   // B arrived during conversion
        __syncthreads();

        float acc[2][8][4];
        #pragma unroll
        for (int i = 0; i < 2; ++i)
            #pragma unroll
            for (int j = 0; j < 8; ++j)
                #pragma unroll
                for (int c = 0; c < 4; ++c) acc[i][j][c] = 0.f;

        #pragma unroll
        for (int ks = 0; ks < 8; ++ks) {
            int a_kc = ks * 2 + a_cadd;
            int b_kc = ks * 2 + b_cadd;

            uint32_t a[2][4];
            #pragma unroll
            for (int mf = 0; mf < 2; ++mf)
                ldsm4(a[mf][0], a[mf][1], a[mf][2], a[mf][3],
                      aB + swz_off(a_r0 + mf * 16, a_kc));

            uint32_t b[8][2];
            #pragma unroll
            for (int p = 0; p < 4; ++p)
                ldsm4(b[p * 2][0], b[p * 2][1], b[p * 2 + 1][0], b[p * 2 + 1][1],
                      bB + swz_off(warp_n + p * 16 + b_nsel, b_kc));

            #pragma unroll
            for (int mf = 0; mf < 2; ++mf)
                #pragma unroll
                for (int nf = 0; nf < 8; ++nf)
                    mma16816(acc[mf][nf], a[mf], b[nf]);
        }

        // --- epilogue: scale by dinv, convert fp16, store
        int qr = lane >> 2, qc = (lane & 3) * 2;
        #pragma unroll
        for (int mf = 0; mf < 2; ++mf) {
            int r0 = tile * 128 + warp_m + mf * 16 + qr;
            int r1 = r0 + 8;
            float d0 = (r0 < NN) ? g_dinv[r0] : 0.f;
            float d1 = (r1 < NN) ? g_dinv[r1] : 0.f;
            #pragma unroll
            for (int nf = 0; nf < 8; ++nf) {
                int col = warp_n + nf * 8 + qc;
                if (r0 < NN) {
                    __half2 o = __floats2half2_rn(acc[mf][nf][0] * d0, acc[mf][nf][1] * d0);
                    *(__half2*)(g_gbuf + (size_t)r0 * DH + col) = o;
                }
                if (r1 < NN) {
                    __half2 o = __floats2half2_rn(acc[mf][nf][2] * d1, acc[mf][nf][3] * d1);
                    *(__half2*)(g_gbuf + (size_t)r1 * DH + col) = o;
                }
            }
        }
        __syncthreads();   // all mainloop reads done before next tile rewrites SA
    }
}

// ---------------- aggregation: fp16 gather (MLP 8), fp32 accum, fp16 h ------
__device__ __forceinline__ void add_h4(float4& a, uint2 u) {
    float2 p0 = __half22float2(*(__half2*)&u.x);
    float2 p1 = __half22float2(*(__half2*)&u.y);
    a.x += p0.x; a.y += p0.y; a.z += p1.x; a.w += p1.y;
}

__global__ void __launch_bounds__(256) k_agg(int layer, const float* __restrict__ bias,
                                             float* __restrict__ out) {
    if (out) {
        int idx = blockIdx.x * 256 + threadIdx.x;
        if (idx < NG * DH) out[idx] = 0.f;
    }
    __shared__ float s_sum[DH];
    __shared__ float s_sq[DH];
    int tid = threadIdx.x;
    if (tid < DH) { s_sum[tid] = 0.f; s_sq[tid] = 0.f; }
    __syncthreads();

    int warp = tid >> 5, lane = tid & 31;
    int base = blockIdx.x * 32 + warp * 4;
    int f = lane * 4;
    float4 b = ((const float4*)bias)[lane];

    float ls0 = 0.f, ls1 = 0.f, ls2 = 0.f, ls3 = 0.f;
    float lq0 = 0.f, lq1 = 0.f, lq2 = 0.f, lq3 = 0.f;

    int nend = base + 4 < NN ? base + 4 : NN;
    for (int node = base; node < nend; ++node) {
        float4 a0 = make_float4(0.f, 0.f, 0.f, 0.f);
        float4 a1 = make_float4(0.f, 0.f, 0.f, 0.f);
        add_h4(a0, *(const uint2*)(g_gbuf + (size_t)node * DH + f));   // self
        int s = g_off[node], e2 = g_off[node + 1];
        int p = s;
        for (; p + 7 < e2; p += 8) {
            int i0 = g_csr[p],     i1 = g_csr[p + 1], i2 = g_csr[p + 2], i3 = g_csr[p + 3];
            int i4 = g_csr[p + 4], i5 = g_csr[p + 5], i6 = g_csr[p + 6], i7 = g_csr[p + 7];
            uint2 u0 = *(const uint2*)(g_gbuf + (size_t)i0 * DH + f);
            uint2 u1 = *(const uint2*)(g_gbuf + (size_t)i1 * DH + f);
            uint2 u2 = *(const uint2*)(g_gbuf + (size_t)i2 * DH + f);
            uint2 u3 = *(const uint2*)(g_gbuf + (size_t)i3 * DH + f);
            uint2 u4 = *(const uint2*)(g_gbuf + (size_t)i4 * DH + f);
            uint2 u5 = *(const uint2*)(g_gbuf + (size_t)i5 * DH + f);
            uint2 u6 = *(const uint2*)(g_gbuf + (size_t)i6 * DH + f);
            uint2 u7 = *(const uint2*)(g_gbuf + (size_t)i7 * DH + f);
            add_h4(a0, u0); add_h4(a1, u1); add_h4(a0, u2); add_h4(a1, u3);
            add_h4(a0, u4); add_h4(a1, u5); add_h4(a0, u6); add_h4(a1, u7);
        }
        for (; p + 1 < e2; p += 2) {
            int i0 = g_csr[p], i1 = g_csr[p + 1];
            uint2 u0 = *(const uint2*)(g_gbuf + (size_t)i0 * DH + f);
            uint2 u1 = *(const uint2*)(g_gbuf + (size_t)i1 * DH + f);
            add_h4(a0, u0); add_h4(a1, u1);
        }
        if (p < e2) {
            int i0 = g_csr[p];
            add_h4(a0, *(const uint2*)(g_gbuf + (size_t)i0 * DH + f));
        }
        float di = g_dinv[node];
        float4 h;
        h.x = fmaf(di, a0.x + a1.x, b.x);
        h.y = fmaf(di, a0.y + a1.y, b.y);
        h.z = fmaf(di, a0.z + a1.z, b.z);
        h.w = fmaf(di, a0.w + a1.w, b.w);
        __half2 o0 = __floats2half2_rn(h.x, h.y);
        __half2 o1 = __floats2half2_rn(h.z, h.w);
        uint2 ov;
        ov.x = *(uint32_t*)&o0;
        ov.y = *(uint32_t*)&o1;
        *(uint2*)(g_hag + (size_t)node * DH + f) = ov;

        ls0 += h.x; lq0 += h.x * h.x;
        ls1 += h.y; lq1 += h.y * h.y;
        ls2 += h.z; lq2 += h.z * h.z;
        ls3 += h.w; lq3 += h.w * h.w;
    }
    atomicAdd(&s_sum[f + 0], ls0); atomicAdd(&s_sq[f + 0], lq0);
    atomicAdd(&s_sum[f + 1], ls1); atomicAdd(&s_sq[f + 1], lq1);
    atomicAdd(&s_sum[f + 2], ls2); atomicAdd(&s_sq[f + 2], lq2);
    atomicAdd(&s_sum[f + 3], ls3); atomicAdd(&s_sq[f + 3], lq3);
    __syncthreads();
    if (tid < DH) {
        atomicAdd(&g_sum[layer * DH + tid], s_sum[tid]);
        atomicAdd(&g_sq[layer * DH + tid], s_sq[tid]);
    }
}

// ---------------- pooling: batch-preloaded rows, pre-scaled atomics ----------
__global__ void __launch_bounds__(256) k_pool(const int* __restrict__ bidx,
                                              const float* __restrict__ gamma,
                                              const float* __restrict__ beta,
                                              float* __restrict__ out) {
    int tid = threadIdx.x;
    int warp = (blockIdx.x * 8 + (tid >> 5));
    int base = warp * 8;
    if (base >= NN) return;
    int lane = tid & 31;
    int f = lane * 4;
    const int L2 = (NL - 1) * DH;
    float s[4], t[4];
    #pragma unroll
    for (int c = 0; c < 4; ++c) {
        float m = g_sum[L2 + f + c] * (1.f / NN);
        float var = g_sq[L2 + f + c] * (1.f / NN) - m * m;
        float rs = rsqrtf(var + BN_EPS);
        s[c] = gamma[f + c] * rs;
        t[c] = beta[f + c] - m * s[c];
    }

    int cnt = base + 8 < NN ? 8 : NN - base;
    uint2 r[8];
    int bi[8];
    #pragma unroll
    for (int i = 0; i < 8; ++i) {
        if (i < cnt) {
            r[i] = *(const uint2*)(g_hag + (size_t)(base + i) * DH + f);
            bi[i] = bidx[base + i];
        }
    }

    float a0 = 0.f, a1 = 0.f, a2 = 0.f, a3 = 0.f;
    int cur = bi[0];
    #pragma unroll
    for (int i = 0; i < 8; ++i) {
        if (i >= cnt) break;
        if (bi[i] != cur) {
            float inv = 1.f / fmaxf((float)g_cnt[cur], 1.f);
            float* o = out + (size_t)cur * DH + f;
            atomicAdd(o + 0, a0 * inv); atomicAdd(o + 1, a1 * inv);
            atomicAdd(o + 2, a2 * inv); atomicAdd(o + 3, a3 * inv);
            a0 = a1 = a2 = a3 = 0.f;
            cur = bi[i];
        }
        float2 p0 = __half22float2(*(__half2*)&r[i].x);
        float2 p1 = __half22float2(*(__half2*)&r[i].y);
        a0 += elu1(fmaf(p0.x, s[0], t[0]));
        a1 += elu1(fmaf(p0.y, s[1], t[1]));
        a2 += elu1(fmaf(p1.x, s[2], t[2]));
        a3 += elu1(fmaf(p1.y, s[3], t[3]));
    }
    float inv = 1.f / fmaxf((float)g_cnt[cur], 1.f);
    float* o = out + (size_t)cur * DH + f;
    atomicAdd(o + 0, a0 * inv); atomicAdd(o + 1, a1 * inv);
    atomicAdd(o + 2, a2 * inv); atomicAdd(o + 3, a3 * inv);
}

// ---------------- launch ----------------
extern "C" void kernel_launch(void* const* d_in, const int* in_sizes, int n_in,
                              void* d_out, int out_size) {
    const float* x      = (const float*)d_in[0];
    const float* Ws     = (const float*)d_in[1];
    const float* bs     = (const float*)d_in[2];
    const float* gammas = (const float*)d_in[3];
    const float* betas  = (const float*)d_in[4];
    const int*   ei     = (const int*)d_in[5];
    const int*   bidx   = (const int*)d_in[6];
    float*       out    = (float*)d_out;

    const int* src = ei;
    const int* dst = ei + NE;

    cudaFuncSetAttribute(k_gemm_tc, cudaFuncAttributeMaxDynamicSharedMemorySize, SM_TOTAL);

    int agg_grid = (NN + 31) / 32;

    k_init_all<<<(NN + 255) / 256, 256>>>(Ws);                      // 1
    k_deg<<<(NE + 255) / 256, 256>>>(dst, bidx);                    // 2
    k_bsum<<<SCAN_NB, SCAN_T>>>();                                  // 3 (+dinv)
    k_gemm_tc<<<GEMM_GRID, 256, SM_TOTAL>>>(0, x, gammas, betas);   // 4 <- ncu slot
    k_lscan<<<SCAN_NB, SCAN_T>>>();                                 // 5 (+bscan)
    k_fill<<<(NE + 255) / 256, 256>>>(src, dst);                    // 6

    k_agg<<<agg_grid, 256>>>(0, bs, nullptr);                       // 7
    k_gemm_tc<<<GEMM_GRID, 256, SM_TOTAL>>>(1, x, gammas + DH, betas + DH);
    k_agg<<<agg_grid, 256>>>(1, bs + DH, nullptr);
    k_gemm_tc<<<GEMM_GRID, 256, SM_TOTAL>>>(2, x, gammas + 2 * DH, betas + 2 * DH);
    k_agg<<<agg_grid, 256>>>(2, bs + 2 * DH, out);                  // zeroes out

    int pool_grid = (NN + 63) / 64;
    k_pool<<<pool_grid, 256>>>(bidx, gammas + 2 * DH, betas + 2 * DH, out);
}

// round 17
// speedup vs baseline: 1.5005x; 1.0335x over previous
#include <cuda_runtime.h>
#include <cuda_fp16.h>
#include <math.h>
#include <stdint.h>

#define NN 50000
#define NE 640000
#define DH 128
#define NG 1024
#define NL 3
#define BN_EPS 1e-5f

#define SCAN_T 256
#define SCAN_NB ((NN + SCAN_T - 1) / SCAN_T)   // 196

__device__ __forceinline__ uint32_t smem_to_u32(const void* p) {
    uint32_t a;
    asm("{ .reg .u64 t; cvta.to.shared.u64 t, %1; cvt.u32.u64 %0, t; }" : "=r"(a) : "l"(p));
    return a;
}

// ---------------- scratch ----------------
__device__ int   g_deg[NN];
__device__ int   g_off[NN + 1];
__device__ int   g_cur[NN];
__device__ float g_dinv[NN];
__device__ int   g_csr[NE];
__device__ int   g_bsum[SCAN_NB];
__device__ __half g_gbuf[(size_t)NN * DH];     // fp16 messages
__device__ __half g_hag[(size_t)NN * DH];      // fp16 aggregated h
__device__ float g_sum[NL * DH];
__device__ float g_sq[NL * DH];
__device__ int   g_cnt[NG];
__device__ unsigned short g_whi[NL * 16384];   // W^T fp16, swizzled 32KB/layer

__device__ __forceinline__ float elu1(float v) {
    return v > 0.f ? v : (__expf(v) - 1.f);
}

__device__ __forceinline__ int swz_off(int r, int kchunk) {
    return r * 256 + ((kchunk ^ (r & 7)) << 4);
}

// ---------------- launch 1: init everything + W convert ----------------
__global__ void k_init_all(const float* __restrict__ Ws) {
    int i = blockIdx.x * 256 + threadIdx.x;
    if (i < NN) g_deg[i] = 0;
    if (i < NL * DH) { g_sum[i] = 0.f; g_sq[i] = 0.f; }
    if (i < NG) g_cnt[i] = 0;
    if (i < NL * 16384) {
        int l = i >> 14;
        int rem = i & 16383;
        int n = rem & 127;
        int k = rem >> 7;
        float w = Ws[(size_t)l * 16384 + k * 128 + n];
        int off = swz_off(n, k >> 3) + (k & 7) * 2;
        g_whi[l * 16384 + (off >> 1)] = __half_as_ushort(__float2half_rn(w));
    }
}

// ---------------- launch 2: degree histogram + graph counts ----------------
__global__ void k_deg(const int* __restrict__ dst, const int* __restrict__ bidx) {
    int e = blockIdx.x * blockDim.x + threadIdx.x;
    if (e < NE) atomicAdd(&g_deg[dst[e]], 1);
    if (e < NN) atomicAdd(&g_cnt[bidx[e]], 1);
}

// ---------------- launch 3: block sums + dinv ----------------
__global__ void __launch_bounds__(SCAN_T) k_bsum() {
    int i = blockIdx.x * SCAN_T + threadIdx.x;
    int v = (i < NN) ? g_deg[i] : 0;
    if (i < NN) g_dinv[i] = rsqrtf((float)(v + 1));   // +1 self loop
    #pragma unroll
    for (int o = 16; o; o >>= 1) v += __shfl_down_sync(0xffffffffu, v, o);
    __shared__ int ws[SCAN_T / 32];
    if ((threadIdx.x & 31) == 0) ws[threadIdx.x >> 5] = v;
    __syncthreads();
    if (threadIdx.x < SCAN_T / 32) {
        int s = ws[threadIdx.x];
        #pragma unroll
        for (int o = SCAN_T / 64; o; o >>= 1) s += __shfl_down_sync(0xffu, s, o);
        if (threadIdx.x == 0) g_bsum[blockIdx.x] = s;
    }
}

// ---------------- local scan with self-computed block offset ----------------
__global__ void __launch_bounds__(SCAN_T) k_lscan() {
    int tid = threadIdx.x;
    int lane = tid & 31, wid = tid >> 5;
    int bid = blockIdx.x;

    __shared__ int s_boff;
    __shared__ int wred[SCAN_T / 32];
    {
        int bv = (tid < bid) ? g_bsum[tid] : 0;
        #pragma unroll
        for (int o = 16; o; o >>= 1) bv += __shfl_down_sync(0xffffffffu, bv, o);
        if (lane == 0) wred[wid] = bv;
        __syncthreads();
        if (tid == 0) {
            int s = 0;
            #pragma unroll
            for (int w = 0; w < SCAN_T / 32; ++w) s += wred[w];
            s_boff = s;
        }
        __syncthreads();
    }

    int i = bid * SCAN_T + tid;
    int v = (i < NN) ? g_deg[i] : 0;
    int incl = v;
    #pragma unroll
    for (int o = 1; o < 32; o <<= 1) {
        int t = __shfl_up_sync(0xffffffffu, incl, o);
        if (lane >= o) incl += t;
    }
    __shared__ int wtot[SCAN_T / 32];
    if (lane == 31) wtot[wid] = incl;
    __syncthreads();
    if (tid < SCAN_T / 32) {
        int s = wtot[tid];
        int si = s;
        #pragma unroll
        for (int o = 1; o < SCAN_T / 32; o <<= 1) {
            int t = __shfl_up_sync(0xffu, si, o);
            if (tid >= o) si += t;
        }
        wtot[tid] = si - s;
    }
    __syncthreads();
    int excl = incl - v + wtot[wid] + s_boff;
    if (i < NN) {
        g_off[i] = excl;
        g_cur[i] = excl;
        if (i == NN - 1) g_off[NN] = excl + v;
    }
}

__global__ void k_fill(const int* __restrict__ src, const int* __restrict__ dst) {
    int e = blockIdx.x * blockDim.x + threadIdx.x;
    if (e < NE) {
        int d = dst[e];
        int pos = atomicAdd(&g_cur[d], 1);
        g_csr[pos] = src[e];
    }
}

// ---------------- HMMA GEMM: grid=391, pure fp16, single pass ----------------
#define SA    0
#define SB    32768
#define SC_OFF 65536
#define SH_OFF 66048
#define SM_TOTAL 66560

__device__ __forceinline__ void ldsm4(uint32_t& r0, uint32_t& r1, uint32_t& r2,
                                      uint32_t& r3, uint32_t addr) {
    asm volatile("ldmatrix.sync.aligned.m8n8.x4.shared.b16 {%0,%1,%2,%3}, [%4];"
                 : "=r"(r0), "=r"(r1), "=r"(r2), "=r"(r3) : "r"(addr));
}
__device__ __forceinline__ void mma16816(float* d, const uint32_t* a, const uint32_t* b) {
    asm volatile(
        "mma.sync.aligned.m16n8k16.row.col.f32.f16.f16.f32 "
        "{%0,%1,%2,%3}, {%4,%5,%6,%7}, {%8,%9}, {%0,%1,%2,%3};"
        : "+f"(d[0]), "+f"(d[1]), "+f"(d[2]), "+f"(d[3])
        : "r"(a[0]), "r"(a[1]), "r"(a[2]), "r"(a[3]), "r"(b[0]), "r"(b[1]));
}
#define CP_ASYNC16(dst, src) \
    asm volatile("cp.async.cg.shared.global [%0], [%1], 16;" :: "r"(dst), "l"(src))
#define CP_COMMIT() asm volatile("cp.async.commit_group;" ::: "memory")
#define CP_WAIT0() asm volatile("cp.async.wait_group 0;" ::: "memory")

__global__ void __launch_bounds__(256, 2) k_gemm_tc(int layer, const float* __restrict__ x,
                                                    const float* __restrict__ gamma,
                                                    const float* __restrict__ beta) {
    extern __shared__ char sm[];
    uint32_t sm_u = smem_to_u32(sm);
    int tid = threadIdx.x;
    int wid = tid >> 5, lane = tid & 31;

    // --- B tile (32KB) via cp.async (in flight during BN setup + conversion)
    {
        const char* wh = (const char*)(g_whi + layer * 16384) + tid * 16;
        uint32_t bh = sm_u + SB + tid * 16;
        #pragma unroll
        for (int i = 0; i < 8; ++i)
            CP_ASYNC16(bh + i * 4096, wh + i * 4096);
        CP_COMMIT();
    }

    // --- BN scale/shift into smem
    float* scp = (float*)(sm + SC_OFF);
    float* shp = (float*)(sm + SH_OFF);
    if (layer > 0 && tid < DH) {
        float m = g_sum[(layer - 1) * DH + tid] * (1.f / NN);
        float var = g_sq[(layer - 1) * DH + tid] * (1.f / NN) - m * m;
        float rs = rsqrtf(var + BN_EPS);
        float scv = gamma[tid] * rs;
        scp[tid] = scv;
        shp[tid] = beta[tid] - m * scv;
    }
    if (layer > 0) __syncthreads();   // publish scp/shp before conversion reads

    // --- convert A' half-row per thread (fused BN+ELU for layer>0)
    {
        int row = tid >> 1, hq = tid & 1;
        int gr = blockIdx.x * 128 + row;
        if (gr < NN) {
            #pragma unroll
            for (int c8 = 0; c8 < 8; ++c8) {
                int kc = hq * 8 + c8;
                int k0 = kc * 8;
                float f[8];
                if (layer == 0) {
                    float4 v0 = *(const float4*)(x + (size_t)gr * DH + k0);
                    float4 v1 = *(const float4*)(x + (size_t)gr * DH + k0 + 4);
                    f[0] = v0.x; f[1] = v0.y; f[2] = v0.z; f[3] = v0.w;
                    f[4] = v1.x; f[5] = v1.y; f[6] = v1.z; f[7] = v1.w;
                } else {
                    int4 u = *(const int4*)(g_hag + (size_t)gr * DH + k0);
                    float2 p0 = __half22float2(*(__half2*)&u.x);
                    float2 p1 = __half22float2(*(__half2*)&u.y);
                    float2 p2 = __half22float2(*(__half2*)&u.z);
                    float2 p3 = __half22float2(*(__half2*)&u.w);
                    f[0] = p0.x; f[1] = p0.y; f[2] = p1.x; f[3] = p1.y;
                    f[4] = p2.x; f[5] = p2.y; f[6] = p3.x; f[7] = p3.y;
                    #pragma unroll
                    for (int c = 0; c < 8; ++c)
                        f[c] = elu1(fmaf(f[c], scp[k0 + c], shp[k0 + c]));
                }
                uint32_t hp[4];
                #pragma unroll
                for (int p = 0; p < 4; ++p) {
                    __half2 h2 = __floats2half2_rn(f[p * 2], f[p * 2 + 1]);
                    hp[p] = *(uint32_t*)&h2;
                }
                *(int4*)(sm + SA + swz_off(row, kc)) = make_int4(hp[0], hp[1], hp[2], hp[3]);
            }
        } else {
            int4 z = make_int4(0, 0, 0, 0);
            #pragma unroll
            for (int c8 = 0; c8 < 8; ++c8)
                *(int4*)(sm + SA + swz_off(row, hq * 8 + c8)) = z;
        }
    }
    CP_WAIT0();
    __syncthreads();

    int warp_m = (wid & 3) * 32;
    int warp_n = (wid >> 2) * 64;

    float acc[2][8][4];
    #pragma unroll
    for (int i = 0; i < 2; ++i)
        #pragma unroll
        for (int j = 0; j < 8; ++j)
            #pragma unroll
            for (int c = 0; c < 4; ++c) acc[i][j][c] = 0.f;

    int sub = lane >> 3, l7 = lane & 7;
    int a_r0 = warp_m + (sub & 1) * 8 + l7;
    int a_cadd = sub >> 1;
    int b_nsel = (sub >> 1) * 8 + l7;
    int b_cadd = sub & 1;

    uint32_t aB = sm_u + SA, bB = sm_u + SB;
    #pragma unroll
    for (int ks = 0; ks < 8; ++ks) {
        int a_kc = ks * 2 + a_cadd;
        int b_kc = ks * 2 + b_cadd;

        uint32_t a[2][4];
        #pragma unroll
        for (int mf = 0; mf < 2; ++mf)
            ldsm4(a[mf][0], a[mf][1], a[mf][2], a[mf][3],
                  aB + swz_off(a_r0 + mf * 16, a_kc));

        uint32_t b[8][2];
        #pragma unroll
        for (int p = 0; p < 4; ++p)
            ldsm4(b[p * 2][0], b[p * 2][1], b[p * 2 + 1][0], b[p * 2 + 1][1],
                  bB + swz_off(warp_n + p * 16 + b_nsel, b_kc));

        #pragma unroll
        for (int mf = 0; mf < 2; ++mf)
            #pragma unroll
            for (int nf = 0; nf < 8; ++nf)
                mma16816(acc[mf][nf], a[mf], b[nf]);
    }

    // --- epilogue: scale by dinv, convert fp16, store
    int qr = lane >> 2, qc = (lane & 3) * 2;
    #pragma unroll
    for (int mf = 0; mf < 2; ++mf) {
        int r0 = blockIdx.x * 128 + warp_m + mf * 16 + qr;
        int r1 = r0 + 8;
        float d0 = (r0 < NN) ? g_dinv[r0] : 0.f;
        float d1 = (r1 < NN) ? g_dinv[r1] : 0.f;
        #pragma unroll
        for (int nf = 0; nf < 8; ++nf) {
            int col = warp_n + nf * 8 + qc;
            if (r0 < NN) {
                __half2 o = __floats2half2_rn(acc[mf][nf][0] * d0, acc[mf][nf][1] * d0);
                *(__half2*)(g_gbuf + (size_t)r0 * DH + col) = o;
            }
            if (r1 < NN) {
                __half2 o = __floats2half2_rn(acc[mf][nf][2] * d1, acc[mf][nf][3] * d1);
                *(__half2*)(g_gbuf + (size_t)r1 * DH + col) = o;
            }
        }
    }
}

// ---------------- aggregation: fp16 gather (MLP 8), fp32 accum, fp16 h ------
__device__ __forceinline__ void add_h4(float4& a, uint2 u) {
    float2 p0 = __half22float2(*(__half2*)&u.x);
    float2 p1 = __half22float2(*(__half2*)&u.y);
    a.x += p0.x; a.y += p0.y; a.z += p1.x; a.w += p1.y;
}

__global__ void __launch_bounds__(256) k_agg(int layer, const float* __restrict__ bias,
                                             float* __restrict__ out) {
    if (out) {
        int idx = blockIdx.x * 256 + threadIdx.x;
        if (idx < NG * DH) out[idx] = 0.f;
    }
    __shared__ float s_sum[DH];
    __shared__ float s_sq[DH];
    int tid = threadIdx.x;
    if (tid < DH) { s_sum[tid] = 0.f; s_sq[tid] = 0.f; }
    __syncthreads();

    int warp = tid >> 5, lane = tid & 31;
    int base = blockIdx.x * 32 + warp * 4;
    int f = lane * 4;
    float4 b = ((const float4*)bias)[lane];

    float ls0 = 0.f, ls1 = 0.f, ls2 = 0.f, ls3 = 0.f;
    float lq0 = 0.f, lq1 = 0.f, lq2 = 0.f, lq3 = 0.f;

    int nend = base + 4 < NN ? base + 4 : NN;
    for (int node = base; node < nend; ++node) {
        float4 a0 = make_float4(0.f, 0.f, 0.f, 0.f);
        float4 a1 = make_float4(0.f, 0.f, 0.f, 0.f);
        add_h4(a0, *(const uint2*)(g_gbuf + (size_t)node * DH + f));   // self
        int s = g_off[node], e2 = g_off[node + 1];
        int p = s;
        for (; p + 7 < e2; p += 8) {
            int i0 = g_csr[p],     i1 = g_csr[p + 1], i2 = g_csr[p + 2], i3 = g_csr[p + 3];
            int i4 = g_csr[p + 4], i5 = g_csr[p + 5], i6 = g_csr[p + 6], i7 = g_csr[p + 7];
            uint2 u0 = *(const uint2*)(g_gbuf + (size_t)i0 * DH + f);
            uint2 u1 = *(const uint2*)(g_gbuf + (size_t)i1 * DH + f);
            uint2 u2 = *(const uint2*)(g_gbuf + (size_t)i2 * DH + f);
            uint2 u3 = *(const uint2*)(g_gbuf + (size_t)i3 * DH + f);
            uint2 u4 = *(const uint2*)(g_gbuf + (size_t)i4 * DH + f);
            uint2 u5 = *(const uint2*)(g_gbuf + (size_t)i5 * DH + f);
            uint2 u6 = *(const uint2*)(g_gbuf + (size_t)i6 * DH + f);
            uint2 u7 = *(const uint2*)(g_gbuf + (size_t)i7 * DH + f);
            add_h4(a0, u0); add_h4(a1, u1); add_h4(a0, u2); add_h4(a1, u3);
            add_h4(a0, u4); add_h4(a1, u5); add_h4(a0, u6); add_h4(a1, u7);
        }
        for (; p + 1 < e2; p += 2) {
            int i0 = g_csr[p], i1 = g_csr[p + 1];
            uint2 u0 = *(const uint2*)(g_gbuf + (size_t)i0 * DH + f);
            uint2 u1 = *(const uint2*)(g_gbuf + (size_t)i1 * DH + f);
            add_h4(a0, u0); add_h4(a1, u1);
        }
        if (p < e2) {
            int i0 = g_csr[p];
            add_h4(a0, *(const uint2*)(g_gbuf + (size_t)i0 * DH + f));
        }
        float di = g_dinv[node];
        float4 h;
        h.x = fmaf(di, a0.x + a1.x, b.x);
        h.y = fmaf(di, a0.y + a1.y, b.y);
        h.z = fmaf(di, a0.z + a1.z, b.z);
        h.w = fmaf(di, a0.w + a1.w, b.w);
        __half2 o0 = __floats2half2_rn(h.x, h.y);
        __half2 o1 = __floats2half2_rn(h.z, h.w);
        uint2 ov;
        ov.x = *(uint32_t*)&o0;
        ov.y = *(uint32_t*)&o1;
        *(uint2*)(g_hag + (size_t)node * DH + f) = ov;

        ls0 += h.x; lq0 += h.x * h.x;
        ls1 += h.y; lq1 += h.y * h.y;
        ls2 += h.z; lq2 += h.z * h.z;
        ls3 += h.w; lq3 += h.w * h.w;
    }
    atomicAdd(&s_sum[f + 0], ls0); atomicAdd(&s_sq[f + 0], lq0);
    atomicAdd(&s_sum[f + 1], ls1); atomicAdd(&s_sq[f + 1], lq1);
    atomicAdd(&s_sum[f + 2], ls2); atomicAdd(&s_sq[f + 2], lq2);
    atomicAdd(&s_sum[f + 3], ls3); atomicAdd(&s_sq[f + 3], lq3);
    __syncthreads();
    if (tid < DH) {
        atomicAdd(&g_sum[layer * DH + tid], s_sum[tid]);
        atomicAdd(&g_sq[layer * DH + tid], s_sq[tid]);
    }
}

// ---------------- pooling: batch-preloaded rows, pre-scaled atomics ----------
__global__ void __launch_bounds__(256) k_pool(const int* __restrict__ bidx,
                                              const float* __restrict__ gamma,
                                              const float* __restrict__ beta,
                                              float* __restrict__ out) {
    int tid = threadIdx.x;
    int warp = (blockIdx.x * 8 + (tid >> 5));
    int base = warp * 8;
    if (base >= NN) return;
    int lane = tid & 31;
    int f = lane * 4;
    const int L2 = (NL - 1) * DH;
    float s[4], t[4];
    #pragma unroll
    for (int c = 0; c < 4; ++c) {
        float m = g_sum[L2 + f + c] * (1.f / NN);
        float var = g_sq[L2 + f + c] * (1.f / NN) - m * m;
        float rs = rsqrtf(var + BN_EPS);
        s[c] = gamma[f + c] * rs;
        t[c] = beta[f + c] - m * s[c];
    }

    int cnt = base + 8 < NN ? 8 : NN - base;
    uint2 r[8];
    int bi[8];
    #pragma unroll
    for (int i = 0; i < 8; ++i) {
        if (i < cnt) {
            r[i] = *(const uint2*)(g_hag + (size_t)(base + i) * DH + f);
            bi[i] = bidx[base + i];
        }
    }

    float a0 = 0.f, a1 = 0.f, a2 = 0.f, a3 = 0.f;
    int cur = bi[0];
    #pragma unroll
    for (int i = 0; i < 8; ++i) {
        if (i >= cnt) break;
        if (bi[i] != cur) {
            float inv = 1.f / fmaxf((float)g_cnt[cur], 1.f);
            float* o = out + (size_t)cur * DH + f;
            atomicAdd(o + 0, a0 * inv); atomicAdd(o + 1, a1 * inv);
            atomicAdd(o + 2, a2 * inv); atomicAdd(o + 3, a3 * inv);
            a0 = a1 = a2 = a3 = 0.f;
            cur = bi[i];
        }
        float2 p0 = __half22float2(*(__half2*)&r[i].x);
        float2 p1 = __half22float2(*(__half2*)&r[i].y);
        a0 += elu1(fmaf(p0.x, s[0], t[0]));
        a1 += elu1(fmaf(p0.y, s[1], t[1]));
        a2 += elu1(fmaf(p1.x, s[2], t[2]));
        a3 += elu1(fmaf(p1.y, s[3], t[3]));
    }
    float inv = 1.f / fmaxf((float)g_cnt[cur], 1.f);
    float* o = out + (size_t)cur * DH + f;
    atomicAdd(o + 0, a0 * inv); atomicAdd(o + 1, a1 * inv);
    atomicAdd(o + 2, a2 * inv); atomicAdd(o + 3, a3 * inv);
}

// ---------------- launch ----------------
extern "C" void kernel_launch(void* const* d_in, const int* in_sizes, int n_in,
                              void* d_out, int out_size) {
    const float* x      = (const float*)d_in[0];
    const float* Ws     = (const float*)d_in[1];
    const float* bs     = (const float*)d_in[2];
    const float* gammas = (const float*)d_in[3];
    const float* betas  = (const float*)d_in[4];
    const int*   ei     = (const int*)d_in[5];
    const int*   bidx   = (const int*)d_in[6];
    float*       out    = (float*)d_out;

    const int* src = ei;
    const int* dst = ei + NE;

    // one-time resources (no device memory; identical GPU work every call)
    static cudaStream_t s2 = [] {
        cudaStream_t t;
        cudaStreamCreateWithFlags(&t, cudaStreamNonBlocking);
        return t;
    }();
    static cudaEvent_t ev_fork = [] {
        cudaEvent_t e;
        cudaEventCreateWithFlags(&e, cudaEventDisableTiming);
        return e;
    }();
    static cudaEvent_t ev_join = [] {
        cudaEvent_t e;
        cudaEventCreateWithFlags(&e, cudaEventDisableTiming);
        return e;
    }();

    cudaFuncSetAttribute(k_gemm_tc, cudaFuncAttributeMaxDynamicSharedMemorySize, SM_TOTAL);

    int gemm_grid = (NN + 127) / 128;   // 391
    int agg_grid = (NN + 31) / 32;

    k_init_all<<<(NN + 255) / 256, 256>>>(Ws);                      // 1
    k_deg<<<(NE + 255) / 256, 256>>>(dst, bidx);                    // 2
    k_bsum<<<SCAN_NB, SCAN_T>>>();                                  // 3 (+dinv)
    cudaEventRecord(ev_fork, 0);
    k_gemm_tc<<<gemm_grid, 256, SM_TOTAL>>>(0, x, gammas, betas);   // 4 <- ncu slot
    // CSR build overlaps with layer-0 GEMM on side stream
    cudaStreamWaitEvent(s2, ev_fork, 0);
    k_lscan<<<SCAN_NB, SCAN_T, 0, s2>>>();
    k_fill<<<(NE + 255) / 256, 256, 0, s2>>>(src, dst);
    cudaEventRecord(ev_join, s2);
    cudaStreamWaitEvent(0, ev_join, 0);

    k_agg<<<agg_grid, 256>>>(0, bs, nullptr);
    k_gemm_tc<<<gemm_grid, 256, SM_TOTAL>>>(1, x, gammas + DH, betas + DH);
    k_agg<<<agg_grid, 256>>>(1, bs + DH, nullptr);
    k_gemm_tc<<<gemm_grid, 256, SM_TOTAL>>>(2, x, gammas + 2 * DH, betas + 2 * DH);
    k_agg<<<agg_grid, 256>>>(2, bs + 2 * DH, out);                  // zeroes out

    int pool_grid = (NN + 63) / 64;
    k_pool<<<pool_grid, 256>>>(bidx, gammas + 2 * DH, betas + 2 * DH, out);
}